// round 7
// baseline (speedup 1.0000x reference)
#include <cuda_runtime.h>
#include <cstdint>

// Problem constants (fixed by setup_inputs)
#define BATCH 4
#define LEN   2048
#define DIM   64
#define KMAX  64

// Scratch: packed key bits per token, uint2 = (lo bits d0..31, hi bits d32..63).
// __device__ global array is the allowed scratch mechanism (no cudaMalloc).
__device__ uint2 g_keys[BATCH * LEN];

// ---------------------------------------------------------------------------
// Kernel 1: pack key sign bits. One warp per token.
// lane d reads key_up[tok*64 + d] and key_up[tok*64 + 32 + d]; two ballots
// assemble the 32-bit group words. Fully coalesced 128B loads per warp.
// ---------------------------------------------------------------------------
__global__ void pack_keys_kernel(const float* __restrict__ key_up) {
    int warp = (blockIdx.x * blockDim.x + threadIdx.x) >> 5;
    int lane = threadIdx.x & 31;
    if (warp >= BATCH * LEN) return;
    const float* p = key_up + (size_t)warp * DIM;
    unsigned lo = __ballot_sync(0xFFFFFFFFu, p[lane]      > 0.0f);
    unsigned hi = __ballot_sync(0xFFFFFFFFu, p[lane + 32] > 0.0f);
    if (lane == 0) g_keys[warp] = make_uint2(lo, hi);
}

// ---------------------------------------------------------------------------
// Kernel 2: candidate scan. 256 threads = 8 warps = 8 queries per block.
// Block loads its batch's 2048 packed keys (16 KB) into smem once.
// Each warp packs its own query via ballot, then scans keys 32-at-a-time:
// ballot of per-lane match -> ordered index emission via popc prefix.
// This preserves the "smallest matching indices first" order exactly.
// Output dtype is FLOAT32 (int bit pattern -1 reinterprets as NaN -> the
// round-4 failure). Emit (float)j and -1.0f.
// ---------------------------------------------------------------------------
__global__ void __launch_bounds__(256, 8)
find_cands_kernel(const float* __restrict__ query_up, float* __restrict__ out) {
    __shared__ uint2 skeys[LEN];

    // 256 query-groups (of 8) per batch
    int b    = blockIdx.x >> 8;
    int qgrp = blockIdx.x & 255;

    // Cooperative key load: 2048 uint2 / 256 threads = 8 LDG.64 each
    const uint2* gk = g_keys + (size_t)b * LEN;
    #pragma unroll
    for (int i = 0; i < LEN / 256; ++i)
        skeys[i * 256 + threadIdx.x] = gk[i * 256 + threadIdx.x];
    __syncthreads();

    int warp = threadIdx.x >> 5;
    int lane = threadIdx.x & 31;
    int qi   = qgrp * 8 + warp;

    // Pack this warp's query in-registers (coalesced 128B loads)
    const float* qp = query_up + ((size_t)b * LEN + qi) * DIM;
    unsigned qlo = __ballot_sync(0xFFFFFFFFu, qp[lane]      > 0.0f);
    unsigned qhi = __ballot_sync(0xFFFFFFFFu, qp[lane + 32] > 0.0f);

    float* __restrict__ o = out + ((size_t)b * LEN + qi) * KMAX;
    unsigned lt_mask = (1u << lane) - 1u;

    int count = 0;
    #pragma unroll 4
    for (int c = 0; c < LEN / 32; ++c) {
        int j = c * 32 + lane;
        uint2 k = skeys[j];
        bool m = (k.x == qlo) | (k.y == qhi);
        unsigned mask = __ballot_sync(0xFFFFFFFFu, m);
        if (mask) {
            int pos = count + __popc(mask & lt_mask);
            if (m && pos < KMAX) o[pos] = (float)j;
            count += __popc(mask);
            if (count >= KMAX) break;   // warp-uniform (mask is uniform)
        }
    }

    // Pad remaining slots with -1.0f (d_out is poisoned, must write all 64)
    for (int p = count + lane; p < KMAX; p += 32)
        o[p] = -1.0f;
}

// ---------------------------------------------------------------------------
// Launch: inputs per metadata order = query_up (f32), key_up (f32), head_idx.
// head_idx is 0 and unused (the reference ignores it beyond head selection).
// ---------------------------------------------------------------------------
extern "C" void kernel_launch(void* const* d_in, const int* in_sizes, int n_in,
                              void* d_out, int out_size) {
    const float* query_up = (const float*)d_in[0];
    const float* key_up   = (const float*)d_in[1];
    float* out = (float*)d_out;

    // 8192 tokens, 8 warps per 256-thread block -> 1024 blocks
    pack_keys_kernel<<<(BATCH * LEN) / 8, 256>>>(key_up);
    // 8 queries per block -> 1024 blocks
    find_cands_kernel<<<(BATCH * LEN) / 8, 256>>>(query_up, out);
}

// round 8
// speedup vs baseline: 1.1750x; 1.1750x over previous
#include <cuda_runtime.h>
#include <cstdint>

// Problem constants (fixed by setup_inputs)
#define BATCH 4
#define LEN   2048
#define DIM   64
#define KMAX  64

// Scratch: packed key bits per token, uint2 = (lo bits d0..31, hi bits d32..63).
__device__ uint2 g_keys[BATCH * LEN];

// ---------------------------------------------------------------------------
// Kernel 1: pack key sign bits. One warp per token, two ballots.
// ---------------------------------------------------------------------------
__global__ void pack_keys_kernel(const float* __restrict__ key_up) {
    int warp = (blockIdx.x * blockDim.x + threadIdx.x) >> 5;
    int lane = threadIdx.x & 31;
    if (warp >= BATCH * LEN) return;
    const float* p = key_up + (size_t)warp * DIM;
    unsigned lo = __ballot_sync(0xFFFFFFFFu, p[lane]      > 0.0f);
    unsigned hi = __ballot_sync(0xFFFFFFFFu, p[lane + 32] > 0.0f);
    if (lane == 0) g_keys[warp] = make_uint2(lo, hi);
}

// ---------------------------------------------------------------------------
// Kernel 2: candidate scan. 512 threads = 16 warps = 16 queries per block.
// Block caches its batch's 2048 packed keys (16 KB) in smem.
// FAST PATH (always, statistically): dependency-free OR-reduce over 2 keys
// per lane per iteration (LDS.128), ONE ballot at the end. No match -> -1s.
// RARE PATH: ordered ballot-scan (exact R5 semantics) if any lane matched.
// Output dtype is float32: emit (float)index and -1.0f.
// ---------------------------------------------------------------------------
__global__ void __launch_bounds__(512, 3)
find_cands_kernel(const float* __restrict__ query_up, float* __restrict__ out) {
    __shared__ uint2 skeys[LEN];

    int b    = blockIdx.x >> 7;       // 128 blocks per batch
    int qgrp = blockIdx.x & 127;

    // Cooperative key fill: 1024 uint4 / 512 threads = 2 LDG.128 each
    const uint4* gk4 = (const uint4*)(g_keys + (size_t)b * LEN);
    uint4* sk4 = (uint4*)skeys;
    sk4[threadIdx.x]       = gk4[threadIdx.x];
    sk4[threadIdx.x + 512] = gk4[threadIdx.x + 512];
    __syncthreads();

    int warp = threadIdx.x >> 5;
    int lane = threadIdx.x & 31;
    int qi   = qgrp * 16 + warp;

    // Pack this warp's query in-registers
    const float* qp = query_up + ((size_t)b * LEN + qi) * DIM;
    unsigned qlo = __ballot_sync(0xFFFFFFFFu, qp[lane]      > 0.0f);
    unsigned qhi = __ballot_sync(0xFFFFFFFFu, qp[lane + 32] > 0.0f);

    float* __restrict__ o = out + ((size_t)b * LEN + qi) * KMAX;

    // ---- FAST PATH: ballot-free OR-reduce. Lane l, iter c covers keys
    // 2*(c*32+l) and 2*(c*32+l)+1 via one LDS.128. 32 iters = 2048 keys.
    const uint4* sq = (const uint4*)skeys;
    bool anym = false;
    #pragma unroll 8
    for (int c = 0; c < LEN / 64; ++c) {
        uint4 k = sq[c * 32 + lane];
        anym |= (k.x == qlo) | (k.y == qhi) | (k.z == qlo) | (k.w == qhi);
    }

    if (__builtin_expect(__ballot_sync(0xFFFFFFFFu, anym) == 0u, 1)) {
        // No match anywhere (the statistically certain case): all -1.
        // One STG.64 per lane covers all 64 slots.
        ((float2*)o)[lane] = make_float2(-1.0f, -1.0f);
        return;
    }

    // ---- RARE PATH: ordered ballot scan (exact semantics, R5-proven)
    unsigned lt_mask = (1u << lane) - 1u;
    int count = 0;
    for (int c = 0; c < LEN / 32; ++c) {
        int j = c * 32 + lane;
        uint2 k = skeys[j];
        bool m = (k.x == qlo) | (k.y == qhi);
        unsigned mask = __ballot_sync(0xFFFFFFFFu, m);
        if (mask) {
            int pos = count + __popc(mask & lt_mask);
            if (m && pos < KMAX) o[pos] = (float)j;
            count += __popc(mask);
            if (count >= KMAX) break;   // warp-uniform
        }
    }
    for (int p = count + lane; p < KMAX; p += 32)
        o[p] = -1.0f;
}

// ---------------------------------------------------------------------------
// Launch: inputs = query_up (f32), key_up (f32), head_idx (unused).
// ---------------------------------------------------------------------------
extern "C" void kernel_launch(void* const* d_in, const int* in_sizes, int n_in,
                              void* d_out, int out_size) {
    const float* query_up = (const float*)d_in[0];
    const float* key_up   = (const float*)d_in[1];
    float* out = (float*)d_out;

    // 8192 tokens, 8 warps per 256-thread block
    pack_keys_kernel<<<(BATCH * LEN) / 8, 256>>>(key_up);
    // 16 queries per 512-thread block -> 512 blocks
    find_cands_kernel<<<(BATCH * LEN) / 16, 512>>>(query_up, out);
}